// round 7
// baseline (speedup 1.0000x reference)
#include <cuda_runtime.h>
#include <math.h>

#define BB 32
#define MM 1024
#define NN 1024
#define SS 8      // n-split factor
#define TN 128    // n per block tile (SS*TN = NN)
#define NP (TN/2) // n-pairs per tile = 64
#define MS 8      // m-split: 8 groups of 128 m's; 1 m per thread

typedef unsigned long long u64;

// ---------------- scratch (no allocations allowed) ----------------
__device__ float g_part[SS][BB * MM];       // partial sqrt-sums per n-chunk
__device__ float g_dish[BB * MM];           // sum over all n (not yet /N)
__device__ float g_lpart[256];              // per-combine-block loss partials
__device__ int   g_which[BB];
__device__ float g_Rbest[BB][12];           // R row-major (9) + t_best (3); 48B rows

// ---------------- f32x2 helpers (sm_103a packed fp32) ----------------
__device__ __forceinline__ u64 pack2(float a, float b) {
    u64 r; asm("mov.b64 %0, {%1,%2};" : "=l"(r) : "f"(a), "f"(b)); return r;
}
__device__ __forceinline__ void unpack2(u64 v, float& a, float& b) {
    asm("mov.b64 {%0,%1}, %2;" : "=f"(a), "=f"(b) : "l"(v));
}
__device__ __forceinline__ u64 fma2(u64 a, u64 b, u64 c) {
    u64 r; asm("fma.rn.f32x2 %0, %1, %2, %3;" : "=l"(r) : "l"(a), "l"(b), "l"(c)); return r;
}
__device__ __forceinline__ u64 add2(u64 a, u64 b) {
    u64 r; asm("add.rn.f32x2 %0, %1, %2;" : "=l"(r) : "l"(a), "l"(b)); return r;
}
__device__ __forceinline__ u64 mul2(u64 a, u64 b) {
    u64 r; asm("mul.rn.f32x2 %0, %1, %2;" : "=l"(r) : "l"(a), "l"(b)); return r;
}
__device__ __forceinline__ float sqrt_approx(float x) {
    float r; asm("sqrt.approx.f32 %0, %1;" : "=f"(r) : "f"(x)); return r;
}

// quat (xyzw) + t -> 12 floats: R row-major then t
__device__ __forceinline__ void quat_to_Rt(float qx, float qy, float qz, float qw,
                                           float t0, float t1, float t2, float* o) {
    float nrm = sqrtf(qx * qx + qy * qy + qz * qz + qw * qw);
    float inv = __fdividef(1.0f, nrm + 1e-8f);
    qx *= inv; qy *= inv; qz *= inv; qw *= inv;
    o[0] = 1.0f - 2.0f * (qy * qy + qz * qz);
    o[1] = 2.0f * (qx * qy - qz * qw);
    o[2] = 2.0f * (qx * qz + qy * qw);
    o[3] = 2.0f * (qx * qy + qz * qw);
    o[4] = 1.0f - 2.0f * (qx * qx + qz * qz);
    o[5] = 2.0f * (qy * qz - qx * qw);
    o[6] = 2.0f * (qx * qz - qy * qw);
    o[7] = 2.0f * (qy * qz + qx * qw);
    o[8] = 1.0f - 2.0f * (qx * qx + qy * qy);
    o[9] = t0; o[10] = t1; o[11] = t2;
}

// ---------------- K1: fused prep + 33.5M-pair distance kernel ----------------
// grid (SS, MS, BB), 128 threads. Thread t owns m = t + h*128.
// f32x2 lanes carry (n, n+1) pairs; R/t constants are lane-splat.
// Tile stores NEGATED tg so the translate-subtract is a single add2.
__global__ void __launch_bounds__(128, 10) k_main(const float* __restrict__ pred_r,
                                                  const float* __restrict__ pred_t,
                                                  const float* __restrict__ pred_c,
                                                  const float* __restrict__ points,
                                                  const float* __restrict__ mp,
                                                  const float* __restrict__ tg) {
    const int s = blockIdx.x;
    const int h = blockIdx.y;
    const int b = blockIdx.z;
    const int t = threadIdx.x;

    __shared__ __align__(16) u64 sm[NP][6];   // [n-pair][j]: (mp.x,mp.x'),(mp.y,..),(mp.z,..),(-tg.x,..),(-tg.y,..),(-tg.z,..)

    // ---- n-tile load: thread t<NP packs n-pair (2t, 2t+1) ----
    if (t < NP) {
        const float* mb = mp + ((size_t)(b * NN + s * TN + 2 * t)) * 3;  // 6 consecutive floats
        const float* gb = tg + ((size_t)(b * NN + s * TN + 2 * t)) * 3;
        float a0 = mb[0], a1 = mb[1], a2 = mb[2], a3 = mb[3], a4 = mb[4], a5 = mb[5];
        float c0 = gb[0], c1 = gb[1], c2 = gb[2], c3 = gb[3], c4 = gb[4], c5 = gb[5];
        sm[t][0] = pack2(a0, a3);
        sm[t][1] = pack2(a1, a4);
        sm[t][2] = pack2(a2, a5);
        sm[t][3] = pack2(-c0, -c3);
        sm[t][4] = pack2(-c1, -c4);
        sm[t][5] = pack2(-c2, -c5);
    }

    // ---- inline prep: R/t for this thread's single m, lane-splat constants ----
    u64 C[12];
    {
        int m = t + h * 128;
        int i = b * MM + m;
        float4 q = reinterpret_cast<const float4*>(pred_r)[i];
        float t0 = points[3 * i + 0] + pred_t[3 * i + 0];
        float t1 = points[3 * i + 1] + pred_t[3 * i + 1];
        float t2 = points[3 * i + 2] + pred_t[3 * i + 2];
        float o[12];
        quat_to_Rt(q.x, q.y, q.z, q.w, t0, t1, t2, o);
        #pragma unroll
        for (int j = 0; j < 12; j++) C[j] = pack2(o[j], o[j]);
    }

    // ---- argmax of clamped pred_c: only the 32 (s==0,h==0) blocks ----
    if (s == 0 && h == 0) {
        __shared__ float sv[128];
        __shared__ int   si[128];
        float cmax = -1e30f; int cidx = 0;
        #pragma unroll
        for (int k = 0; k < 8; k++) {                 // increasing m -> first-max tie-break
            int m = t + k * 128;
            float c = fmaxf(pred_c[b * MM + m], 1e-6f);
            if (c > cmax) { cmax = c; cidx = m; }
        }
        sv[t] = cmax; si[t] = cidx;
        __syncthreads();
        #pragma unroll
        for (int off = 64; off > 0; off >>= 1) {
            if (t < off) {
                if (sv[t + off] > sv[t] || (sv[t + off] == sv[t] && si[t + off] < si[t])) {
                    sv[t] = sv[t + off]; si[t] = si[t + off];
                }
            }
            __syncthreads();
        }
        if (t == 0) g_which[b] = si[0];
    }
    __syncthreads();   // covers sm tile for all blocks

    // ---- main loop: 2 cells per iter (1 m x 2 packed n's) ----
    float acc = 0.0f;

    #pragma unroll 2
    for (int n = 0; n < NP; n++) {
        ulonglong2 p01 = *reinterpret_cast<const ulonglong2*>(&sm[n][0]);
        ulonglong2 p23 = *reinterpret_cast<const ulonglong2*>(&sm[n][2]);
        ulonglong2 p45 = *reinterpret_cast<const ulonglong2*>(&sm[n][4]);
        u64 m0 = p01.x, m1 = p01.y, m2 = p23.x;
        u64 v0 = p23.y, v1 = p45.x, v2 = p45.y;     // v = -tg
        u64 s0 = add2(v0, C[9]);                    // t - tg
        u64 s1 = add2(v1, C[10]);
        u64 s2 = add2(v2, C[11]);
        u64 d0 = fma2(m0, C[0], fma2(m1, C[3], fma2(m2, C[6], s0)));
        u64 d1 = fma2(m0, C[1], fma2(m1, C[4], fma2(m2, C[7], s1)));
        u64 d2 = fma2(m0, C[2], fma2(m1, C[5], fma2(m2, C[8], s2)));
        u64 sq = fma2(d0, d0, fma2(d1, d1, mul2(d2, d2)));
        float sa, sb; unpack2(sq, sa, sb);
        acc += sqrt_approx(sa);
        acc += sqrt_approx(sb);
    }

    g_part[s][(size_t)b * MM + h * 128 + t] = acc;
}

// ---------------- K2: combine partials + loss partials + R_best ----------------
__global__ void k_combine(const float* __restrict__ wptr,
                          const float* __restrict__ pred_r,
                          const float* __restrict__ pred_t,
                          const float* __restrict__ pred_c,
                          const float* __restrict__ points) {
    if (blockIdx.x == 256) {
        int t = threadIdx.x;
        if (t < BB) {
            int which = g_which[t];
            int i = t * MM + which;
            float4 q = reinterpret_cast<const float4*>(pred_r)[i];
            float t0 = points[3 * i + 0] + pred_t[3 * i + 0];
            float t1 = points[3 * i + 1] + pred_t[3 * i + 1];
            float t2 = points[3 * i + 2] + pred_t[3 * i + 2];
            float o[12];
            quat_to_Rt(q.x, q.y, q.z, q.w, t0, t1, t2, o);
            #pragma unroll
            for (int j = 0; j < 12; j++) g_Rbest[t][j] = o[j];
        }
        return;
    }
    int i = blockIdx.x * 128 + threadIdx.x;  // 256 blocks x 128 = 32768
    float w = *wptr;
    float dsum = 0.0f;
    #pragma unroll
    for (int ss = 0; ss < SS; ss++) dsum += g_part[ss][i];
    g_dish[i] = dsum;
    float c = fmaxf(pred_c[i], 1e-6f);
    float term = dsum * (1.0f / (float)NN) * c - w * __logf(c);

    __shared__ float sbuf[128];
    int t = threadIdx.x;
    sbuf[t] = term;
    __syncthreads();
    #pragma unroll
    for (int off = 64; off > 0; off >>= 1) {
        if (t < off) sbuf[t] += sbuf[t + off];
        __syncthreads();
    }
    if (t == 0) g_lpart[blockIdx.x] = sbuf[0];
}

// ---------------- K3: transform new_points / new_target + final scalars ----------------
__global__ void k_transform(const float* __restrict__ points,
                            const float* __restrict__ target,
                            float* __restrict__ out) {
    if (blockIdx.x == 256) {
        int t = threadIdx.x;   // 256 threads
        __shared__ float sbuf[256];
        __shared__ float sdb;
        sbuf[t] = g_lpart[t];
        if (t < 32) {
            float db = g_dish[t * MM + g_which[t]];
            #pragma unroll
            for (int off = 16; off > 0; off >>= 1)
                db += __shfl_down_sync(0xffffffffu, db, off);
            if (t == 0) sdb = db;
        }
        __syncthreads();
        #pragma unroll
        for (int off = 128; off > 0; off >>= 1) {
            if (t < off) sbuf[t] += sbuf[t + off];
            __syncthreads();
        }
        if (t == 0) {
            out[0] = sbuf[0] / (float)(BB * MM);
            out[1] = sdb * (1.0f / (float)NN) / (float)BB;
        }
        return;
    }
    int id = blockIdx.x * 256 + threadIdx.x; // 256 blocks x 256 = 65536 = BB*(MM+NN)
    int b = id >> 11;
    int r = id & 2047;

    // g_Rbest row: 48B stride -> 16B aligned; 3 vector loads
    const float4* rb4 = reinterpret_cast<const float4*>(&g_Rbest[b][0]);
    float4 ra = rb4[0], rbv = rb4[1], rc = rb4[2];
    float R0 = ra.x, R1 = ra.y, R2 = ra.z, R3 = ra.w;
    float R4 = rbv.x, R5 = rbv.y, R6 = rbv.z, R7 = rbv.w;
    float R8 = rc.x,  T0 = rc.y,  T1 = rc.z,  T2 = rc.w;

    const float* src;
    float* dst;
    if (r < MM) {
        src = points + ((size_t)b * MM + r) * 3;
        dst = out + 2 + ((size_t)b * MM + r) * 3;
    } else {
        int n = r - MM;
        src = target + ((size_t)b * NN + n) * 3;
        dst = out + 2 + (size_t)BB * MM * 3 + ((size_t)b * NN + n) * 3;
    }
    float d0 = src[0] - T0;
    float d1 = src[1] - T1;
    float d2 = src[2] - T2;
    dst[0] = d0 * R0 + d1 * R3 + d2 * R6;
    dst[1] = d0 * R1 + d1 * R4 + d2 * R7;
    dst[2] = d0 * R2 + d1 * R5 + d2 * R8;
}

// ---------------- launch ----------------
extern "C" void kernel_launch(void* const* d_in, const int* in_sizes, int n_in,
                              void* d_out, int out_size) {
    const float* pred_r       = (const float*)d_in[0];
    const float* pred_t       = (const float*)d_in[1];
    const float* pred_c       = (const float*)d_in[2];
    const float* target       = (const float*)d_in[3];
    const float* model_points = (const float*)d_in[4];
    // d_in[5] = idx (unused, refine path)
    const float* points       = (const float*)d_in[6];
    const float* wptr         = (const float*)d_in[7];
    // d_in[8] = refine (unused)
    float* out = (float*)d_out;

    k_main<<<dim3(SS, MS, BB), 128>>>(pred_r, pred_t, pred_c, points, model_points, target);
    k_combine<<<257, 128>>>(wptr, pred_r, pred_t, pred_c, points);
    k_transform<<<257, 256>>>(points, target, out);
}

// round 8
// speedup vs baseline: 1.1682x; 1.1682x over previous
#include <cuda_runtime.h>
#include <math.h>

#define BB 32
#define MM 1024
#define NN 1024
#define SS 4      // n-split factor
#define TN 256    // n per block tile (SS*TN = NN)
#define NP (TN/2) // n-pairs per tile = 128
#define MS 8      // m-split: 8 groups of 128 m's; 1 m per thread

typedef unsigned long long u64;

// ---------------- scratch (no allocations allowed) ----------------
__device__ float g_part[SS][BB * MM];       // partial sqrt-sums per n-chunk
__device__ float g_dish[BB * MM];           // sum over all n (not yet /N)
__device__ float g_lpart[256];              // per-combine-block loss partials
__device__ int   g_which[BB];
__device__ float g_Rbest[BB][12];           // R row-major (9) + t_best (3); 48B rows

// ---------------- f32x2 helpers (sm_103a packed fp32) ----------------
__device__ __forceinline__ u64 pack2(float a, float b) {
    u64 r; asm("mov.b64 %0, {%1,%2};" : "=l"(r) : "f"(a), "f"(b)); return r;
}
__device__ __forceinline__ void unpack2(u64 v, float& a, float& b) {
    asm("mov.b64 {%0,%1}, %2;" : "=f"(a), "=f"(b) : "l"(v));
}
__device__ __forceinline__ u64 fma2(u64 a, u64 b, u64 c) {
    u64 r; asm("fma.rn.f32x2 %0, %1, %2, %3;" : "=l"(r) : "l"(a), "l"(b), "l"(c)); return r;
}
__device__ __forceinline__ u64 add2(u64 a, u64 b) {
    u64 r; asm("add.rn.f32x2 %0, %1, %2;" : "=l"(r) : "l"(a), "l"(b)); return r;
}
__device__ __forceinline__ u64 mul2(u64 a, u64 b) {
    u64 r; asm("mul.rn.f32x2 %0, %1, %2;" : "=l"(r) : "l"(a), "l"(b)); return r;
}
__device__ __forceinline__ float sqrt_approx(float x) {
    float r; asm("sqrt.approx.f32 %0, %1;" : "=f"(r) : "f"(x)); return r;
}

// quat (xyzw) + t -> 12 floats: R row-major then t
__device__ __forceinline__ void quat_to_Rt(float qx, float qy, float qz, float qw,
                                           float t0, float t1, float t2, float* o) {
    float nrm = sqrtf(qx * qx + qy * qy + qz * qz + qw * qw);
    float inv = __fdividef(1.0f, nrm + 1e-8f);
    qx *= inv; qy *= inv; qz *= inv; qw *= inv;
    o[0] = 1.0f - 2.0f * (qy * qy + qz * qz);
    o[1] = 2.0f * (qx * qy - qz * qw);
    o[2] = 2.0f * (qx * qz + qy * qw);
    o[3] = 2.0f * (qx * qy + qz * qw);
    o[4] = 1.0f - 2.0f * (qx * qx + qz * qz);
    o[5] = 2.0f * (qy * qz - qx * qw);
    o[6] = 2.0f * (qx * qz - qy * qw);
    o[7] = 2.0f * (qy * qz + qx * qw);
    o[8] = 1.0f - 2.0f * (qx * qx + qy * qy);
    o[9] = t0; o[10] = t1; o[11] = t2;
}

// ---------------- K1: fused prep + 33.5M-pair distance kernel ----------------
// grid (SS, MS, BB), 128 threads. Thread t owns m = t + h*128.
// f32x2 lanes carry (n, n+1) pairs; R/t constants are lane-splat.
// Tile stores NEGATED tg so the translate-subtract is a single add2.
__global__ void __launch_bounds__(128, 10) k_main(const float* __restrict__ pred_r,
                                                  const float* __restrict__ pred_t,
                                                  const float* __restrict__ pred_c,
                                                  const float* __restrict__ points,
                                                  const float* __restrict__ mp,
                                                  const float* __restrict__ tg) {
    const int s = blockIdx.x;
    const int h = blockIdx.y;
    const int b = blockIdx.z;
    const int t = threadIdx.x;

    __shared__ __align__(16) u64 sm[NP][6];   // [n-pair][j]: (mp.x,mp.x'),(mp.y,..),(mp.z,..),(-tg.x,..),(-tg.y,..),(-tg.z,..)

    // ---- n-tile load: every thread packs n-pair (2t, 2t+1) via float2 loads ----
    {
        const float2* mb = reinterpret_cast<const float2*>(mp + (size_t)(b * NN + s * TN) * 3);
        const float2* gb = reinterpret_cast<const float2*>(tg + (size_t)(b * NN + s * TN) * 3);
        float2 A0 = mb[3 * t], A1 = mb[3 * t + 1], A2 = mb[3 * t + 2]; // (x0,y0)(z0,x1)(y1,z1)
        float2 G0 = gb[3 * t], G1 = gb[3 * t + 1], G2 = gb[3 * t + 2];
        sm[t][0] = pack2(A0.x, A1.y);   // x0, x1
        sm[t][1] = pack2(A0.y, A2.x);   // y0, y1
        sm[t][2] = pack2(A1.x, A2.y);   // z0, z1
        sm[t][3] = pack2(-G0.x, -G1.y);
        sm[t][4] = pack2(-G0.y, -G2.x);
        sm[t][5] = pack2(-G1.x, -G2.y);
    }

    // ---- inline prep: R/t for this thread's single m, lane-splat constants ----
    u64 C[12];
    {
        int m = t + h * 128;
        int i = b * MM + m;
        float4 q = reinterpret_cast<const float4*>(pred_r)[i];
        float t0 = points[3 * i + 0] + pred_t[3 * i + 0];
        float t1 = points[3 * i + 1] + pred_t[3 * i + 1];
        float t2 = points[3 * i + 2] + pred_t[3 * i + 2];
        float o[12];
        quat_to_Rt(q.x, q.y, q.z, q.w, t0, t1, t2, o);
        #pragma unroll
        for (int j = 0; j < 12; j++) C[j] = pack2(o[j], o[j]);
    }

    // ---- argmax + R_best: only the 32 (s==0,h==0) blocks ----
    if (s == 0 && h == 0) {
        __shared__ float sv[128];
        __shared__ int   si[128];
        float cmax = -1e30f; int cidx = 0;
        #pragma unroll
        for (int k = 0; k < 8; k++) {                 // increasing m -> first-max tie-break
            int m = t + k * 128;
            float c = fmaxf(pred_c[b * MM + m], 1e-6f);
            if (c > cmax) { cmax = c; cidx = m; }
        }
        sv[t] = cmax; si[t] = cidx;
        __syncthreads();
        #pragma unroll
        for (int off = 64; off > 0; off >>= 1) {
            if (t < off) {
                if (sv[t + off] > sv[t] || (sv[t + off] == sv[t] && si[t + off] < si[t])) {
                    sv[t] = sv[t + off]; si[t] = si[t + off];
                }
            }
            __syncthreads();
        }
        if (t == 0) {
            int which = si[0];
            g_which[b] = which;
            int i = b * MM + which;
            float4 q = reinterpret_cast<const float4*>(pred_r)[i];
            float t0 = points[3 * i + 0] + pred_t[3 * i + 0];
            float t1 = points[3 * i + 1] + pred_t[3 * i + 1];
            float t2 = points[3 * i + 2] + pred_t[3 * i + 2];
            float o[12];
            quat_to_Rt(q.x, q.y, q.z, q.w, t0, t1, t2, o);
            #pragma unroll
            for (int j = 0; j < 12; j++) g_Rbest[b][j] = o[j];
        }
    }
    __syncthreads();   // covers sm tile for all blocks

    // ---- main loop: 2 cells per iter (1 m x 2 packed n's), dual accumulators ----
    float accA = 0.0f, accB = 0.0f;

    #pragma unroll 4
    for (int n = 0; n < NP; n++) {
        ulonglong2 p01 = *reinterpret_cast<const ulonglong2*>(&sm[n][0]);
        ulonglong2 p23 = *reinterpret_cast<const ulonglong2*>(&sm[n][2]);
        ulonglong2 p45 = *reinterpret_cast<const ulonglong2*>(&sm[n][4]);
        u64 m0 = p01.x, m1 = p01.y, m2 = p23.x;
        u64 v0 = p23.y, v1 = p45.x, v2 = p45.y;     // v = -tg
        u64 s0 = add2(v0, C[9]);                    // t - tg
        u64 s1 = add2(v1, C[10]);
        u64 s2 = add2(v2, C[11]);
        u64 d0 = fma2(m0, C[0], fma2(m1, C[3], fma2(m2, C[6], s0)));
        u64 d1 = fma2(m0, C[1], fma2(m1, C[4], fma2(m2, C[7], s1)));
        u64 d2 = fma2(m0, C[2], fma2(m1, C[5], fma2(m2, C[8], s2)));
        u64 sq = fma2(d0, d0, fma2(d1, d1, mul2(d2, d2)));
        float sa, sb; unpack2(sq, sa, sb);
        accA += sqrt_approx(sa);
        accB += sqrt_approx(sb);
    }

    g_part[s][(size_t)b * MM + h * 128 + t] = accA + accB;
}

// ---------------- K2: combine partials + loss partials ----------------
__global__ void k_combine(const float* __restrict__ wptr,
                          const float* __restrict__ pred_c) {
    int i = blockIdx.x * 128 + threadIdx.x;  // 256 blocks x 128 = 32768
    float w = *wptr;
    float dsum = 0.0f;
    #pragma unroll
    for (int ss = 0; ss < SS; ss++) dsum += g_part[ss][i];
    g_dish[i] = dsum;
    float c = fmaxf(pred_c[i], 1e-6f);
    float term = dsum * (1.0f / (float)NN) * c - w * __logf(c);

    __shared__ float sbuf[128];
    int t = threadIdx.x;
    sbuf[t] = term;
    __syncthreads();
    #pragma unroll
    for (int off = 64; off > 0; off >>= 1) {
        if (t < off) sbuf[t] += sbuf[t + off];
        __syncthreads();
    }
    if (t == 0) g_lpart[blockIdx.x] = sbuf[0];
}

// ---------------- K3: transform new_points / new_target + final scalars ----------------
__global__ void k_transform(const float* __restrict__ points,
                            const float* __restrict__ target,
                            float* __restrict__ out) {
    if (blockIdx.x == 256) {
        int t = threadIdx.x;   // 256 threads
        __shared__ float sbuf[256];
        __shared__ float sdb;
        sbuf[t] = g_lpart[t];
        if (t < 32) {
            float db = g_dish[t * MM + g_which[t]];
            #pragma unroll
            for (int off = 16; off > 0; off >>= 1)
                db += __shfl_down_sync(0xffffffffu, db, off);
            if (t == 0) sdb = db;
        }
        __syncthreads();
        #pragma unroll
        for (int off = 128; off > 0; off >>= 1) {
            if (t < off) sbuf[t] += sbuf[t + off];
            __syncthreads();
        }
        if (t == 0) {
            out[0] = sbuf[0] / (float)(BB * MM);
            out[1] = sdb * (1.0f / (float)NN) / (float)BB;
        }
        return;
    }
    int id = blockIdx.x * 256 + threadIdx.x; // 256 blocks x 256 = 65536 = BB*(MM+NN)
    int b = id >> 11;
    int r = id & 2047;

    // g_Rbest row: 48B stride -> 16B aligned; 3 vector loads
    const float4* rb4 = reinterpret_cast<const float4*>(&g_Rbest[b][0]);
    float4 ra = rb4[0], rbv = rb4[1], rc = rb4[2];
    float R0 = ra.x, R1 = ra.y, R2 = ra.z, R3 = ra.w;
    float R4 = rbv.x, R5 = rbv.y, R6 = rbv.z, R7 = rbv.w;
    float R8 = rc.x,  T0 = rc.y,  T1 = rc.z,  T2 = rc.w;

    const float* src;
    float* dst;
    if (r < MM) {
        src = points + ((size_t)b * MM + r) * 3;
        dst = out + 2 + ((size_t)b * MM + r) * 3;
    } else {
        int n = r - MM;
        src = target + ((size_t)b * NN + n) * 3;
        dst = out + 2 + (size_t)BB * MM * 3 + ((size_t)b * NN + n) * 3;
    }
    float d0 = src[0] - T0;
    float d1 = src[1] - T1;
    float d2 = src[2] - T2;
    dst[0] = d0 * R0 + d1 * R3 + d2 * R6;
    dst[1] = d0 * R1 + d1 * R4 + d2 * R7;
    dst[2] = d0 * R2 + d1 * R5 + d2 * R8;
}

// ---------------- launch ----------------
extern "C" void kernel_launch(void* const* d_in, const int* in_sizes, int n_in,
                              void* d_out, int out_size) {
    const float* pred_r       = (const float*)d_in[0];
    const float* pred_t       = (const float*)d_in[1];
    const float* pred_c       = (const float*)d_in[2];
    const float* target       = (const float*)d_in[3];
    const float* model_points = (const float*)d_in[4];
    // d_in[5] = idx (unused, refine path)
    const float* points       = (const float*)d_in[6];
    const float* wptr         = (const float*)d_in[7];
    // d_in[8] = refine (unused)
    float* out = (float*)d_out;

    k_main<<<dim3(SS, MS, BB), 128>>>(pred_r, pred_t, pred_c, points, model_points, target);
    k_combine<<<256, 128>>>(wptr, pred_c);
    k_transform<<<257, 256>>>(points, target, out);
}